// round 2
// baseline (speedup 1.0000x reference)
#include <cuda_runtime.h>
#include <math.h>

#define VOCAB 32000
#define EMB 32
#define REC 16
#define SEQ 256
#define BATCH 32
#define NROWS (SEQ*BATCH)      // 8192
#define TP 160                 // threads per pass CTA (5 warps)
#define VCH 640                // vocab per pass CTA (160 threads * 4 vocab)

// -------- scratch (static device globals; no allocation allowed) --------
__device__ float  g_xbuf[SEQ*BATCH*EMB];    // gathered embeddings [s][b][e]
__device__ float2 g_hd2[SEQ*BATCH*REC];     // hidden, duplicated (h,h) pairs
__device__ float  g_Vt[REC*VOCAB];          // V transposed [e][v]
__device__ float  g_sums[NROWS];            // per-row sum(exp(logit))
__device__ float  g_lse[NROWS];             // log(sum)

// -------- packed fp32x2 helpers (Blackwell FFMA2 path) --------
__device__ __forceinline__ float2 ffma2(float2 a, float2 b, float2 c) {
    float2 d;
    asm("fma.rn.f32x2 %0, %1, %2, %3;"
        : "=l"(reinterpret_cast<unsigned long long&>(d))
        : "l"(reinterpret_cast<unsigned long long&>(a)),
          "l"(reinterpret_cast<unsigned long long&>(b)),
          "l"(reinterpret_cast<unsigned long long&>(c)));
    return d;
}
__device__ __forceinline__ float2 fadd2(float2 a, float2 b) {
    float2 d;
    asm("add.rn.f32x2 %0, %1, %2;"
        : "=l"(reinterpret_cast<unsigned long long&>(d))
        : "l"(reinterpret_cast<unsigned long long&>(a)),
          "l"(reinterpret_cast<unsigned long long&>(b)));
    return d;
}

// -------- small kernels --------
__global__ void k_zero() {
    int i = blockIdx.x * blockDim.x + threadIdx.x;
    g_sums[i] = 0.f;
}

__global__ void k_transV(const float* __restrict__ V) {
    int v = blockIdx.x * blockDim.x + threadIdx.x;   // 0..31999
    const float4* v4 = (const float4*)(V + v * REC);
    float4 a0 = v4[0], a1 = v4[1], a2 = v4[2], a3 = v4[3];
    float vals[REC] = {a0.x,a0.y,a0.z,a0.w, a1.x,a1.y,a1.z,a1.w,
                       a2.x,a2.y,a2.z,a2.w, a3.x,a3.y,a3.z,a3.w};
#pragma unroll
    for (int e = 0; e < REC; e++) g_Vt[e * VOCAB + v] = vals[e];
}

__global__ void k_gather(const int* __restrict__ idx, const float* __restrict__ emb) {
    int i = blockIdx.x * blockDim.x + threadIdx.x;   // 0..262143
    int row = i >> 5;        // s*BATCH + b
    int e   = i & 31;
    int tok = idx[row];
    g_xbuf[i] = emb[tok * EMB + e];
}

// -------- recurrence: 1 warp per batch, 2 lanes per recurrent unit --------
__global__ void k_rnn(const float* __restrict__ U, const float* __restrict__ W,
                      const float* __restrict__ b1, const float* __restrict__ b2,
                      const float* __restrict__ h0) {
    __shared__ float xs[SEQ * EMB];    // 32 KB: this batch's input slab
    __shared__ float hsm[REC];
    int b = blockIdx.x;
    int lane = threadIdx.x;            // 32 threads

#pragma unroll 8
    for (int i = lane; i < SEQ * EMB; i += 32)
        xs[i] = g_xbuf[((i >> 5) * BATCH + b) * EMB + (i & 31)];

    int j = lane >> 1;                 // recurrent unit 0..15
    int half = lane & 1;               // split of the dot product
    float Ur[16], Wr[8];
#pragma unroll
    for (int e = 0; e < 16; e++) Ur[e] = U[j * EMB + half * 16 + e];
#pragma unroll
    for (int k = 0; k < 8; k++)  Wr[k] = W[j * REC + half * 8 + k];
    float bias = b1[j] + b2[j];

    if (lane < REC) hsm[lane] = h0[lane];
    __syncwarp();

    for (int t = 0; t < SEQ; t++) {
        float h = hsm[j];
        if (!half) g_hd2[(t * BATCH + b) * REC + j] = make_float2(h, h);
        if (t == SEQ - 1) break;

        float acc0 = 0.f, acc1 = 0.f;
        const float* x = &xs[t * EMB + half * 16];
#pragma unroll
        for (int e = 0; e < 16; e += 2) { acc0 += Ur[e] * x[e]; acc1 += Ur[e+1] * x[e+1]; }
        const float* hp = &hsm[half * 8];
#pragma unroll
        for (int k = 0; k < 8; k += 2)  { acc0 += Wr[k] * hp[k]; acc1 += Wr[k+1] * hp[k+1]; }
        float acc = acc0 + acc1;
        acc += __shfl_xor_sync(0xffffffffu, acc, 1);
        float hn = tanhf(bias + acc);
        __syncwarp();
        if (!half) hsm[j] = hn;
        __syncwarp();
    }
}

// -------- pass 1: sum(exp(logit)) per row --------
__global__ void __launch_bounds__(TP) k_pass1() {
    int s = blockIdx.y, chunk = blockIdx.x, tid = threadIdx.x;
    int v0 = chunk * VCH + 2 * tid;
    int v1 = v0 + 320;

    float2 Va[REC], Vb[REC];
#pragma unroll
    for (int e = 0; e < REC; e++) {
        Va[e] = *(const float2*)&g_Vt[e * VOCAB + v0];
        Vb[e] = *(const float2*)&g_Vt[e * VOCAB + v1];
    }

    __shared__ float2 hsh[BATCH * REC];
    __shared__ float  ssum[BATCH];
    for (int i = tid; i < BATCH * REC; i += TP) hsh[i] = g_hd2[s * BATCH * REC + i];
    if (tid < BATCH) ssum[tid] = 0.f;
    __syncthreads();

#pragma unroll 2
    for (int b = 0; b < BATCH; b++) {
        float2 a0 = make_float2(0.f, 0.f), a1 = make_float2(0.f, 0.f);
#pragma unroll
        for (int e = 0; e < REC; e++) {
            float2 h2 = hsh[b * REC + e];
            a0 = ffma2(Va[e], h2, a0);
            a1 = ffma2(Vb[e], h2, a1);
        }
        float p = __expf(a0.x) + __expf(a0.y) + __expf(a1.x) + __expf(a1.y);
#pragma unroll
        for (int o = 16; o > 0; o >>= 1) p += __shfl_xor_sync(0xffffffffu, p, o);
        if ((tid & 31) == 0) atomicAdd(&ssum[b], p);
    }
    __syncthreads();
    if (tid < BATCH) atomicAdd(&g_sums[s * BATCH + tid], ssum[tid]);
}

__global__ void k_lse() {
    int i = blockIdx.x * blockDim.x + threadIdx.x;
    g_lse[i] = logf(g_sums[i]);
}

// -------- pass 2: recompute logits, write logit - lse --------
__global__ void __launch_bounds__(TP) k_pass2(float* __restrict__ out) {
    int s = blockIdx.y, chunk = blockIdx.x, tid = threadIdx.x;
    int v0 = chunk * VCH + 2 * tid;
    int v1 = v0 + 320;

    float2 Va[REC], Vb[REC];
#pragma unroll
    for (int e = 0; e < REC; e++) {
        Va[e] = *(const float2*)&g_Vt[e * VOCAB + v0];
        Vb[e] = *(const float2*)&g_Vt[e * VOCAB + v1];
    }

    __shared__ float2 hsh[BATCH * REC];
    __shared__ float  lsh[BATCH];
    for (int i = tid; i < BATCH * REC; i += TP) hsh[i] = g_hd2[s * BATCH * REC + i];
    if (tid < BATCH) lsh[tid] = -g_lse[s * BATCH + tid];
    __syncthreads();

#pragma unroll 2
    for (int b = 0; b < BATCH; b++) {
        float2 a0 = make_float2(0.f, 0.f), a1 = make_float2(0.f, 0.f);
#pragma unroll
        for (int e = 0; e < REC; e++) {
            float2 h2 = hsh[b * REC + e];
            a0 = ffma2(Va[e], h2, a0);
            a1 = ffma2(Vb[e], h2, a1);
        }
        float nl = lsh[b];
        float2 nl2 = make_float2(nl, nl);
        float2 r0 = fadd2(a0, nl2);
        float2 r1 = fadd2(a1, nl2);
        size_t rowoff = (size_t)(s * BATCH + b) * VOCAB;
        *(float2*)&out[rowoff + v0] = r0;
        *(float2*)&out[rowoff + v1] = r1;
    }
}

extern "C" void kernel_launch(void* const* d_in, const int* in_sizes, int n_in,
                              void* d_out, int out_size) {
    const int*   input_batch = (const int*)  d_in[0];
    const float* embedding   = (const float*)d_in[1];
    const float* U           = (const float*)d_in[2];
    const float* W           = (const float*)d_in[3];
    const float* V           = (const float*)d_in[4];
    const float* b1          = (const float*)d_in[5];
    const float* b2          = (const float*)d_in[6];
    const float* h0          = (const float*)d_in[7];
    float* out = (float*)d_out;

    k_zero  <<<NROWS / 256, 256>>>();
    k_transV<<<VOCAB / 256, 256>>>(V);
    k_gather<<<(SEQ * BATCH * EMB) / 256, 256>>>(input_batch, embedding);
    k_rnn   <<<BATCH, 32>>>(U, W, b1, b2, h0);
    k_pass1 <<<dim3(VOCAB / VCH, SEQ), TP>>>();
    k_lse   <<<NROWS / 256, 256>>>();
    k_pass2 <<<dim3(VOCAB / VCH, SEQ), TP>>>(out);
}